// round 1
// baseline (speedup 1.0000x reference)
#include <cuda_runtime.h>

// ---------------- problem constants (fixed shapes) ----------------
#define B_    32
#define E_    256
#define N_    512          // 2E nodes
#define HID   64           // hidden
#define H_    4            // heads
#define F_    64           // per-head feature
#define C_    256          // H*F
#define S_    255          // E-1 shot steps
#define NE_ELEMS (B_*N_*C_)          // 4,194,304
#define ADJ_ELEMS (B_*14*N_*N_)      // 117,440,512

// ---------------- scratch (static device globals; no allocs) ----------------
__device__ float g_x  [B_*N_*HID];
__device__ float g_h  [B_*N_*C_];
__device__ float g_o1 [B_*N_*C_];
__device__ float g_src[B_*H_*N_];
__device__ float g_dst[B_*H_*N_];
__device__ float g_m  [B_*H_*N_];
__device__ float g_rz [B_*H_*N_];

// ============================================================
// Kernel 1: adjacency. Positions of special pairs are data-independent;
// only shot-pair relation index reads shot_type.
// ============================================================
__device__ __forceinline__ float adj_val(int b, int r, int n, int m, const int* __restrict__ shot) {
    if (n == m) return 0.f;
    int p = n < m ? n : m;
    int q = n < m ? m : n;
    int d = q - p;
    int pm = p & 3;
    bool basep = (d == 2);                                       // every (p,p+2) is a base edge
    bool shotp = (d == 3 && pm == 0 && p <= 508) ||              // even step: (4k,4k+3)
                 (d == 1 && pm == 3 && p <= 507);                // odd step:  (4k+3,4k+4)
    if (r == 13) return (!basep && !shotp) ? 1.f : 0.f;
    if (r >= 11) {
        int rel = (pm == 0 || pm == 3) ? 11 : 12;
        return (basep && rel == r) ? 1.f : 0.f;
    }
    if (shotp) {
        int s = p >> 1;                                          // works for both parities
        return (shot[b * S_ + s] == r) ? 1.f : 0.f;
    }
    return 0.f;
}

__global__ void adj_kernel(const int* __restrict__ shot, float* __restrict__ out) {
    long long idx = (long long)blockIdx.x * blockDim.x + threadIdx.x;  // one float4 group
    int m0 = (int)(idx & 127) << 2;
    int n  = (int)(idx >> 7) & 511;
    int br = (int)(idx >> 16);
    int r = br % 14;
    int b = br / 14;
    float4 v;
    v.x = adj_val(b, r, n, m0 + 0, shot);
    v.y = adj_val(b, r, n, m0 + 1, shot);
    v.z = adj_val(b, r, n, m0 + 2, shot);
    v.w = adj_val(b, r, n, m0 + 3, shot);
    reinterpret_cast<float4*>(out)[idx] = v;
}

// ============================================================
// Kernel 2: node features. x = concat(relu(coord@Wc+bc), emb[player]) @ Wm + bm
// Block: 256 thr handles 32 nodes of one batch.
// ============================================================
__global__ void feat_kernel(const int* __restrict__ player,
                            const float* __restrict__ Ax, const float* __restrict__ Ay,
                            const float* __restrict__ Bx, const float* __restrict__ By,
                            const float* __restrict__ emb,
                            const float* __restrict__ Wc, const float* __restrict__ bc,
                            const float* __restrict__ Wm, const float* __restrict__ bm,
                            float* __restrict__ x) {
    __shared__ float feat[32][64];
    __shared__ float wms[64 * 64];
    int blk = blockIdx.x;
    int b = blk >> 4;
    int n0 = (blk & 15) * 32;
    int tid = threadIdx.x;

    // load Wm (64x64) into smem
    #pragma unroll
    for (int it = 0; it < 16; it++) wms[it * 256 + tid] = Wm[it * 256 + tid];

    // build feature vectors for 32 nodes
    #pragma unroll
    for (int it = 0; it < 8; it++) {
        int o = it * 256 + tid;
        int nl = o >> 6, c = o & 63;
        int n = n0 + nl;
        int e = n >> 1;
        float val;
        if (c < 32) {
            float cx, cy;
            if ((n & 1) == 0) { cx = Ax[b * E_ + e]; cy = Ay[b * E_ + e]; }
            else              { cx = Bx[b * E_ + e]; cy = By[b * E_ + e]; }
            val = fmaxf(cx * Wc[c] + cy * Wc[32 + c] + bc[c], 0.f);
        } else {
            int pid = player[b * 2 + (n & 1)];
            val = emb[pid * 32 + (c - 32)];
        }
        feat[nl][c] = val;
    }
    __syncthreads();

    #pragma unroll
    for (int it = 0; it < 8; it++) {
        int o = it * 256 + tid;
        int nl = o >> 6, k = o & 63;
        float acc = bm[k];
        #pragma unroll
        for (int c = 0; c < 64; c++) acc += feat[nl][c] * wms[c * 64 + k];
        x[(b * N_ + n0 + nl) * HID + k] = acc;
    }
}

// ============================================================
// Kernel 3: SGEMM  C[M,Kout] = A[M,KIN] @ W[KIN,Kout]. 64x64 tile, 4x4/thread.
// ============================================================
template<int KIN>
__global__ void gemm_kernel(const float* __restrict__ A, const float* __restrict__ W,
                            float* __restrict__ C, int Kout) {
    __shared__ float As[16][65];
    __shared__ float Ws[16][64];
    int tid = threadIdx.x;
    int mi = tid >> 4, fi = tid & 15;
    int mt = blockIdx.y * 64, nt = blockIdx.x * 64;

    float4 acc0 = {0,0,0,0}, acc1 = {0,0,0,0}, acc2 = {0,0,0,0}, acc3 = {0,0,0,0};

    for (int kt = 0; kt < KIN; kt += 16) {
        int c = tid & 15, r0 = tid >> 4;
        #pragma unroll
        for (int it = 0; it < 4; it++) {
            int r = r0 + 16 * it;
            As[c][r] = A[(long long)(mt + r) * KIN + kt + c];
        }
        int cc = tid & 63, rr = tid >> 6;
        #pragma unroll
        for (int it = 0; it < 4; it++) {
            int r = rr + 4 * it;
            Ws[r][cc] = W[(kt + r) * Kout + nt + cc];
        }
        __syncthreads();
        #pragma unroll
        for (int k = 0; k < 16; k++) {
            float a0 = As[k][4 * mi + 0], a1 = As[k][4 * mi + 1];
            float a2 = As[k][4 * mi + 2], a3 = As[k][4 * mi + 3];
            float4 bv = *reinterpret_cast<const float4*>(&Ws[k][4 * fi]);
            acc0.x += a0 * bv.x; acc0.y += a0 * bv.y; acc0.z += a0 * bv.z; acc0.w += a0 * bv.w;
            acc1.x += a1 * bv.x; acc1.y += a1 * bv.y; acc1.z += a1 * bv.z; acc1.w += a1 * bv.w;
            acc2.x += a2 * bv.x; acc2.y += a2 * bv.y; acc2.z += a2 * bv.z; acc2.w += a2 * bv.w;
            acc3.x += a3 * bv.x; acc3.y += a3 * bv.y; acc3.z += a3 * bv.z; acc3.w += a3 * bv.w;
        }
        __syncthreads();
    }
    long long base = (long long)(mt + 4 * mi) * Kout + nt + 4 * fi;
    *reinterpret_cast<float4*>(&C[base])             = acc0;
    *reinterpret_cast<float4*>(&C[base + Kout])      = acc1;
    *reinterpret_cast<float4*>(&C[base + 2 * Kout])  = acc2;
    *reinterpret_cast<float4*>(&C[base + 3 * Kout])  = acc3;
}

// ============================================================
// Kernel 4: attention scores s_src/s_dst per (b,h,n).
// Block 256 per (b,n); 64-thread group per head.
// ============================================================
__global__ void score_kernel(const float* __restrict__ h, const float* __restrict__ att,
                             float* __restrict__ ssrc, float* __restrict__ sdst) {
    int bn = blockIdx.x;
    int b = bn >> 9, n = bn & 511;
    int c = threadIdx.x;
    int head = c >> 6, f = c & 63;
    float v = h[(long long)bn * C_ + c];
    float as = v * att[head * 128 + f];
    float ad = v * att[head * 128 + 64 + f];
    #pragma unroll
    for (int off = 16; off >= 1; off >>= 1) {
        as += __shfl_down_sync(0xffffffffu, as, off);
        ad += __shfl_down_sync(0xffffffffu, ad, off);
    }
    __shared__ float pS[8], pD[8];
    int w = c >> 5, lane = c & 31;
    if (lane == 0) { pS[w] = as; pD[w] = ad; }
    __syncthreads();
    if (c < 4) {
        ssrc[(b * H_ + c) * N_ + n] = pS[2 * c] + pS[2 * c + 1];
        sdst[(b * H_ + c) * N_ + n] = pD[2 * c] + pD[2 * c + 1];
    }
}

// ============================================================
// Kernel 5: softmax stats (max, 1/sum) per (b,h,i) over j != i.
// ============================================================
__global__ void mz_kernel(const float* __restrict__ ssrc, const float* __restrict__ sdst,
                          float* __restrict__ gm, float* __restrict__ grz) {
    int bh = blockIdx.x;
    __shared__ float sd[N_];
    int i = threadIdx.x;
    sd[i] = sdst[bh * N_ + i];
    __syncthreads();
    float a = ssrc[bh * N_ + i];
    float m = -1e30f;
    for (int j = 0; j < N_; j++) {
        if (j == i) continue;
        float v = a + sd[j];
        v = v > 0.f ? v : 0.2f * v;
        m = fmaxf(m, v);
    }
    float z = 0.f;
    for (int j = 0; j < N_; j++) {
        if (j == i) continue;
        float v = a + sd[j];
        v = v > 0.f ? v : 0.2f * v;
        z += __expf(v - m);
    }
    gm[bh * N_ + i] = m;
    grz[bh * N_ + i] = 1.f / z;
}

// ============================================================
// Kernel 6: aggregation out[b,i,64h+f] = sum_j w(i,j) h[b,j,64h+f]
// Block: (i-tile 64) x (head) x (batch). 256 thr, 4x4 register tile.
// ============================================================
__global__ void agg_kernel(const float* __restrict__ h,
                           const float* __restrict__ ssrc, const float* __restrict__ sdst,
                           const float* __restrict__ gm, const float* __restrict__ grz,
                           float* __restrict__ out, int dorelu) {
    int b = blockIdx.z, hd = blockIdx.y;
    int i0 = blockIdx.x * 64;
    int bh = b * H_ + hd;
    __shared__ float hjs[32][64];
    __shared__ float wT[32][64];
    __shared__ float aS[64], mS[64], rS[64], bj[32];

    int tid = threadIdx.x;
    int ii = tid >> 4, fi = tid & 15;

    if (tid < 64) {
        int ig = i0 + tid;
        aS[tid] = ssrc[bh * N_ + ig];
        mS[tid] = gm[bh * N_ + ig];
        rS[tid] = grz[bh * N_ + ig];
    }

    float4 acc0 = {0,0,0,0}, acc1 = {0,0,0,0}, acc2 = {0,0,0,0}, acc3 = {0,0,0,0};

    for (int jb = 0; jb < N_; jb += 32) {
        __syncthreads();  // protect previous-iter smem reads (and initial param loads)
        if (tid < 32) bj[tid] = sdst[bh * N_ + jb + tid];
        #pragma unroll
        for (int it = 0; it < 8; it++) {
            int o = it * 256 + tid;
            int j = o >> 6, f = o & 63;
            hjs[j][f] = h[((long long)(b * N_ + jb + j)) * C_ + hd * 64 + f];
        }
        __syncthreads();
        // stage weights: thread owns i = tid&63, 8 j's
        {
            int i = tid & 63;
            int jq = tid >> 6;
            float a = aS[i], m = mS[i], rz = rS[i];
            int ig = i0 + i;
            #pragma unroll
            for (int c = 0; c < 8; c++) {
                int j = jq * 8 + c;
                float v = a + bj[j];
                v = v > 0.f ? v : 0.2f * v;
                float w = (ig == jb + j) ? 0.f : __expf(v - m) * rz;
                wT[j][i] = w;
            }
        }
        __syncthreads();
        #pragma unroll
        for (int j = 0; j < 32; j++) {
            float4 wv = *reinterpret_cast<const float4*>(&wT[j][4 * ii]);
            float4 hv = *reinterpret_cast<const float4*>(&hjs[j][4 * fi]);
            acc0.x += wv.x * hv.x; acc0.y += wv.x * hv.y; acc0.z += wv.x * hv.z; acc0.w += wv.x * hv.w;
            acc1.x += wv.y * hv.x; acc1.y += wv.y * hv.y; acc1.z += wv.y * hv.z; acc1.w += wv.y * hv.w;
            acc2.x += wv.z * hv.x; acc2.y += wv.z * hv.y; acc2.z += wv.z * hv.z; acc2.w += wv.z * hv.w;
            acc3.x += wv.w * hv.x; acc3.y += wv.w * hv.y; acc3.z += wv.w * hv.z; acc3.w += wv.w * hv.w;
        }
    }

    float4 accs[4] = {acc0, acc1, acc2, acc3};
    #pragma unroll
    for (int u = 0; u < 4; u++) {
        float4 v = accs[u];
        if (dorelu) {
            v.x = fmaxf(v.x, 0.f); v.y = fmaxf(v.y, 0.f);
            v.z = fmaxf(v.z, 0.f); v.w = fmaxf(v.w, 0.f);
        }
        int ig = i0 + 4 * ii + u;
        *reinterpret_cast<float4*>(&out[((long long)(b * N_ + ig)) * C_ + hd * 64 + 4 * fi]) = v;
    }
}

// ============================================================
// launch
// ============================================================
extern "C" void kernel_launch(void* const* d_in, const int* in_sizes, int n_in,
                              void* d_out, int out_size) {
    // input order: player, shot_type, Ax, Ay, Bx, By, [encode_length], emb, Wc, bc, Wm, bm, lin1_W, att1, lin2_W, att2
    int off = (n_in >= 16) ? 1 : 0;
    const int*   player = (const int*)  d_in[0];
    const int*   shot   = (const int*)  d_in[1];
    const float* Ax     = (const float*)d_in[2];
    const float* Ay     = (const float*)d_in[3];
    const float* Bx     = (const float*)d_in[4];
    const float* By     = (const float*)d_in[5];
    const float* emb    = (const float*)d_in[6 + off];
    const float* Wc     = (const float*)d_in[7 + off];
    const float* bc     = (const float*)d_in[8 + off];
    const float* Wm     = (const float*)d_in[9 + off];
    const float* bm     = (const float*)d_in[10 + off];
    const float* lin1   = (const float*)d_in[11 + off];
    const float* att1   = (const float*)d_in[12 + off];
    const float* lin2   = (const float*)d_in[13 + off];
    const float* att2   = (const float*)d_in[14 + off];

    float* out_ne  = (float*)d_out;
    float* out_adj = out_ne + NE_ELEMS;

    float *px, *ph, *po1, *psrc, *pdst, *pm, *prz;
    cudaGetSymbolAddress((void**)&px,  g_x);
    cudaGetSymbolAddress((void**)&ph,  g_h);
    cudaGetSymbolAddress((void**)&po1, g_o1);
    cudaGetSymbolAddress((void**)&psrc, g_src);
    cudaGetSymbolAddress((void**)&pdst, g_dst);
    cudaGetSymbolAddress((void**)&pm,  g_m);
    cudaGetSymbolAddress((void**)&prz, g_rz);

    // adjacency (skip if harness only checks node_embedding)
    if (out_size >= NE_ELEMS + ADJ_ELEMS) {
        adj_kernel<<<ADJ_ELEMS / 4 / 256, 256>>>(shot, out_adj);
    }

    // node features
    feat_kernel<<<B_ * 16, 256>>>(player, Ax, Ay, Bx, By, emb, Wc, bc, Wm, bm, px);

    dim3 ggrid(C_ / 64, (B_ * N_) / 64);

    // ---- layer 1 ----
    gemm_kernel<HID><<<ggrid, 256>>>(px, lin1, ph, C_);
    score_kernel<<<B_ * N_, 256>>>(ph, att1, psrc, pdst);
    mz_kernel<<<B_ * H_, N_>>>(psrc, pdst, pm, prz);
    agg_kernel<<<dim3(N_ / 64, H_, B_), 256>>>(ph, psrc, pdst, pm, prz, po1, 1);

    // ---- layer 2 ----
    gemm_kernel<C_><<<ggrid, 256>>>(po1, lin2, ph, C_);
    score_kernel<<<B_ * N_, 256>>>(ph, att2, psrc, pdst);
    mz_kernel<<<B_ * H_, N_>>>(psrc, pdst, pm, prz);
    agg_kernel<<<dim3(N_ / 64, H_, B_), 256>>>(ph, psrc, pdst, pm, prz, out_ne, 0);
}